// round 3
// baseline (speedup 1.0000x reference)
#include <cuda_runtime.h>
#include <stdint.h>

// IN:  (4, 64, 224, 224) fp32
// OUT: (4, 576, 223*223) fp32
// out[ck, oh*223 + ow] = x[bc, oh+ki-1, ow+kj-1] (0 out of bounds)
//   ck = bc*9 + ki*3 + kj
#define H_    224
#define W_    224
#define OH_   223
#define OW_   223
#define OSP   49729u
#define NROWS 513792u             // 2304 * 223
#define WARPS_PER_BLOCK 8u
#define NBLOCKS (NROWS / WARPS_PER_BLOCK)   // 64224 exactly

__global__ void __launch_bounds__(256) unfold_rows_v(const float* __restrict__ x,
                                                     float* __restrict__ out) {
    unsigned warp = blockIdx.x * WARPS_PER_BLOCK + (threadIdx.x >> 5);
    unsigned lane = threadIdx.x & 31u;

    // warp-uniform decomposition
    unsigned ck = warp / OH_;
    unsigned oh = warp - ck * OH_;
    unsigned kj = ck % 3u;
    unsigned t  = ck / 3u;
    unsigned ki = t % 3u;
    unsigned bc = t / 3u;

    int  ih     = (int)(oh + ki) - 1;
    bool row_ok = (unsigned)ih < (unsigned)H_;
    int  shift  = (int)kj - 1;

    const float* __restrict__ src =
        x + ((size_t)bc * H_ + (unsigned)(row_ok ? ih : 0)) * W_;
    size_t d0 = (size_t)ck * OSP + (size_t)oh * OW_;
    float* __restrict__ dst = out + d0;

    // floats until dst is 16B aligned (src rows are always 16B aligned)
    unsigned head = (4u - ((unsigned)d0 & 3u)) & 3u;

    // ---- scalar edges: exactly 3 per row (head + tail) ----
    if (lane < 3u) {
        unsigned ow = (lane < head) ? lane : (head + 220u + (lane - head));
        int iw = (int)ow + shift;
        float v = 0.0f;
        if (row_ok && (unsigned)iw < (unsigned)W_) v = __ldg(src + iw);
        __stcs(dst + ow, v);
    }

    // ---- vector body: 55 aligned float4 stores ----
    float4* dst4 = (float4*)(dst + head);
    // source is float4-aligned iff (head+shift) % 4 == 0 (values 0 or 4;
    // the head=0,shift=-1 OOB case lands in the scalar-load path)
    bool vecload = row_ok && ((((int)head + shift) & 3) == 0);

    for (unsigned j = lane; j < 55u; j += 32u) {
        int iw0 = (int)(head + 4u * j) + shift;
        float4 v;
        if (vecload) {
            v = __ldg((const float4*)(src + iw0));   // iw0 in [0,220], 16B aligned
        } else if (row_ok) {
            v.x = (iw0 >= 0) ? __ldg(src + iw0) : 0.0f;
            v.y = __ldg(src + iw0 + 1);              // iw0+3 <= 222 in this path
            v.z = __ldg(src + iw0 + 2);
            v.w = __ldg(src + iw0 + 3);
        } else {
            v = make_float4(0.0f, 0.0f, 0.0f, 0.0f);
        }
        // streaming store: keep the 51MB input resident in L2 for its 9x reuse
        __stcs(dst4 + j, v);
    }
}

extern "C" void kernel_launch(void* const* d_in, const int* in_sizes, int n_in,
                              void* d_out, int out_size) {
    const float* x = (const float*)d_in[0];
    float* out = (float*)d_out;
    unfold_rows_v<<<NBLOCKS, 256>>>(x, out);
}